// round 9
// baseline (speedup 1.0000x reference)
#include <cuda_runtime.h>
#include <math.h>
#include <stdint.h>

// Problem constants
#define BB 2
#define CC 128
#define HH 64
#define WW 64
#define NH 4
#define DH 32
#define KS 7
#define TOKENS (BB*HH*WW)   // 8192

// Attention tile config
#define TI 8
#define TJ 4
#define NROW 14
#define NCOL 10
#define NCELL 140
#define NCP 144          // padded cells (18 n8 tiles)
#define SQ 36            // Q smem stride   (4 mod 32)
#define SKV 40           // K/V smem stride (8 mod 32)
#define SW 164           // S/W smem stride (4 mod 32)

// Scratch (device globals: no allocation allowed)
__device__ float g_y[TOKENS*CC];
__device__ float g_qkv[TOKENS*3*CC];
__device__ float g_att[TOKENS*CC];
__device__ float g_wq[2*384*128];   // tf32-rounded qkv weights
__device__ float g_wp[2*128*128];   // tf32-rounded proj weights

__device__ __forceinline__ uint32_t f2tf32(float x)
{
    uint32_t r;
    asm("cvt.rna.tf32.f32 %0, %1;" : "=r"(r) : "f"(x));
    return r;
}

__device__ __forceinline__ void mma_tf32(float* d, const uint32_t* a, const uint32_t* b)
{
    asm volatile("mma.sync.aligned.m16n8k8.row.col.f32.tf32.tf32.f32 "
        "{%0,%1,%2,%3}, {%4,%5,%6,%7}, {%8,%9}, {%0,%1,%2,%3};"
        : "+f"(d[0]), "+f"(d[1]), "+f"(d[2]), "+f"(d[3])
        : "r"(a[0]), "r"(a[1]), "r"(a[2]), "r"(a[3]), "r"(b[0]), "r"(b[1]));
}

// ---------------------------------------------------------------------------
// One-shot weight conversion fp32 -> tf32 bit pattern
// ---------------------------------------------------------------------------
__global__ void cvt_w_kernel(const float* __restrict__ qkv_w,
                             const float* __restrict__ proj_w,
                             float* __restrict__ wq,
                             float* __restrict__ wp)
{
    int idx = blockIdx.x * blockDim.x + threadIdx.x;
    const int NQ = 2*384*128;
    const int NP = 2*128*128;
    if (idx < NQ)
        wq[idx] = __uint_as_float(f2tf32(qkv_w[idx]));
    else if (idx < NQ + NP)
        wp[idx - NQ] = __uint_as_float(f2tf32(proj_w[idx - NQ]));
}

// ---------------------------------------------------------------------------
// NCHW -> NHWC transpose
// ---------------------------------------------------------------------------
__global__ void transpose_in_kernel(const float* __restrict__ x, float* __restrict__ y)
{
    __shared__ float tile[32][33];
    int b   = blockIdx.z;
    int hw0 = blockIdx.x * 32;
    int c0  = blockIdx.y * 32;
    int tx = threadIdx.x, ty = threadIdx.y;
    #pragma unroll
    for (int k = 0; k < 32; k += 8)
        tile[ty + k][tx] = x[((b*CC + c0 + ty + k) * (HH*WW)) + hw0 + tx];
    __syncthreads();
    #pragma unroll
    for (int k = 0; k < 32; k += 8)
        y[(b*(HH*WW) + hw0 + ty + k)*CC + c0 + tx] = tile[tx][ty + k];
}

// ---------------------------------------------------------------------------
// tf32 tensor-core GEMM, single-stage full-K smem. (unchanged from R6)
// ---------------------------------------------------------------------------
#define SK 132

__global__ __launch_bounds__(256) void gemm_tc_kernel(
    const float* __restrict__ A,
    const float* __restrict__ W,      // tf32 bits
    const float* __restrict__ bias,
    float* __restrict__ C,
    int N, int scale_q)
{
    extern __shared__ uint32_t smg[];
    uint32_t* As = smg;
    uint32_t* Bs = smg + 64*SK;

    int m0 = blockIdx.x * 64;
    int n0 = blockIdx.y * 64;
    int tid  = threadIdx.x;
    int lane = tid & 31;
    int wid  = tid >> 5;
    int wm = wid & 1;
    int wn = wid >> 1;
    int gp = lane >> 2;
    int tg = lane & 3;

    const float* Ag = A + (m0 + wid)*128 + lane*4;
    const float* Wg = W + (n0 + wid)*128 + lane*4;
    #pragma unroll
    for (int s = 0; s < 8; s++) {
        float4 a = *(const float4*)(Ag + s*8*128);
        float4 b = *(const float4*)(Wg + s*8*128);
        uint4 ua = make_uint4(f2tf32(a.x), f2tf32(a.y), f2tf32(a.z), f2tf32(a.w));
        uint4 ub = make_uint4(__float_as_uint(b.x), __float_as_uint(b.y),
                              __float_as_uint(b.z), __float_as_uint(b.w));
        *(uint4*)&As[(wid + s*8)*SK + lane*4] = ua;
        *(uint4*)&Bs[(wid + s*8)*SK + lane*4] = ub;
    }
    __syncthreads();

    float acc[2][2][4];
    #pragma unroll
    for (int mt = 0; mt < 2; mt++)
        #pragma unroll
        for (int nt = 0; nt < 2; nt++)
            #pragma unroll
            for (int c = 0; c < 4; c++) acc[mt][nt][c] = 0.f;

    #pragma unroll
    for (int ks = 0; ks < 16; ks++) {
        int kb = ks*8;
        uint32_t af[2][4], bf[2][2];
        #pragma unroll
        for (int mt = 0; mt < 2; mt++) {
            int r = wm*32 + mt*16 + gp;
            af[mt][0] = As[r*SK     + kb + tg    ];
            af[mt][1] = As[(r+8)*SK + kb + tg    ];
            af[mt][2] = As[r*SK     + kb + tg + 4];
            af[mt][3] = As[(r+8)*SK + kb + tg + 4];
        }
        #pragma unroll
        for (int nt = 0; nt < 2; nt++) {
            int c = wn*16 + nt*8 + gp;
            bf[nt][0] = Bs[c*SK + kb + tg    ];
            bf[nt][1] = Bs[c*SK + kb + tg + 4];
        }
        #pragma unroll
        for (int mt = 0; mt < 2; mt++)
            #pragma unroll
            for (int nt = 0; nt < 2; nt++)
                mma_tf32(acc[mt][nt], af[mt], bf[nt]);
    }

    const float qs = 0.17677669529663687f;
    #pragma unroll
    for (int mt = 0; mt < 2; mt++) {
        int rbase = m0 + wm*32 + mt*16 + gp;
        #pragma unroll
        for (int nt = 0; nt < 2; nt++) {
            int col = n0 + wn*16 + nt*8 + 2*tg;
            float b0 = bias[col], b1 = bias[col + 1];
            float sc = (scale_q && col < 128) ? qs : 1.f;
            float2 v0 = make_float2((acc[mt][nt][0] + b0)*sc, (acc[mt][nt][1] + b1)*sc);
            float2 v1 = make_float2((acc[mt][nt][2] + b0)*sc, (acc[mt][nt][3] + b1)*sc);
            *(float2*)&C[rbase*N + col]       = v0;
            *(float2*)&C[(rbase + 8)*N + col] = v1;
        }
    }
}
#define GEMM_SMEM (2*64*SK*4)

// ---------------------------------------------------------------------------
// Tensor-core neighborhood attention.
// Block = (head, 8x4 pixel tile), 256 threads.
// S[32x144] = Q@K^T (Q hi+lo tf32, K tf32) -> softmax over 49 window cells ->
// dense zero-padded W[32x144] (hi+lo) -> out[32x32] = W@V (V tf32).
// ---------------------------------------------------------------------------
#define ATTN_SMEM ((2*32*SQ + 2*NCP*SKV + 2*32*SW + 176)*4)

__global__ __launch_bounds__(256) void attn_tc_kernel(
    const float* __restrict__ qkv,
    const float* __restrict__ rpb,
    float* __restrict__ out)
{
    extern __shared__ float sm[];
    float* Qhi = sm;
    float* Qlo = Qhi + 32*SQ;
    float* Ks  = Qlo + 32*SQ;
    float* Vs  = Ks  + NCP*SKV;
    float* Sb  = Vs  + NCP*SKV;   // S, then Whi in-place
    float* Wl  = Sb  + 32*SW;
    float* rpb_s = Wl + 32*SW;

    int j0 = blockIdx.x * TJ;
    int i0 = blockIdx.y * TI;
    int bh = blockIdx.z;
    int b  = bh >> 2;
    int h  = bh & 3;

    int tid  = threadIdx.x;
    int wid  = tid >> 5;
    int lane = tid & 31;
    int gp = lane >> 2;
    int tg = lane & 3;

    int rbase = i0 - 3; rbase = rbase < 0 ? 0 : (rbase > HH-NROW ? HH-NROW : rbase);
    int cbase = j0 - 3; cbase = cbase < 0 ? 0 : (cbase > WW-NCOL ? WW-NCOL : cbase);

    // ---- stage Q (hi/lo), K, V (tf32-rounded), zero pads & Wlo ----
    for (int pix = wid; pix < 32; pix += 8) {
        int i = i0 + (pix >> 2), j = j0 + (pix & 3);
        int tok = (b*HH + i)*WW + j;
        float q  = qkv[tok*384 + h*DH + lane];
        float qh = __uint_as_float(f2tf32(q));
        Qhi[pix*SQ + lane] = qh;
        Qlo[pix*SQ + lane] = __uint_as_float(f2tf32(q - qh));
    }
    for (int r = wid; r < NCELL; r += 8) {
        int gi = r / NCOL, gj = r % NCOL;
        const float* base = qkv + (((b*HH + rbase + gi)*WW) + cbase + gj)*384 + h*DH;
        Ks[r*SKV + lane] = __uint_as_float(f2tf32(base[128 + lane]));
        Vs[r*SKV + lane] = __uint_as_float(f2tf32(base[256 + lane]));
    }
    for (int idx = tid; idx < (NCP-NCELL)*SKV; idx += 256) {
        Ks[NCELL*SKV + idx] = 0.f;
        Vs[NCELL*SKV + idx] = 0.f;
    }
    for (int idx = tid; idx < 32*SW; idx += 256) Wl[idx] = 0.f;
    if (tid < 169) rpb_s[tid] = rpb[h*169 + tid];
    __syncthreads();

    // ---- QK GEMM: S[32][144] ----
    {
        int wm  = wid & 1;             // m16 tile
        int wng = wid >> 1;            // n-tile group: counts {5,5,4,4}
        int t0  = (wng < 2) ? wng*5 : 10 + (wng-2)*4;
        int cnt = (wng < 2) ? 5 : 4;

        float sacc[5][4];
        #pragma unroll
        for (int t = 0; t < 5; t++)
            #pragma unroll
            for (int c = 0; c < 4; c++) sacc[t][c] = 0.f;

        #pragma unroll
        for (int ko = 0; ko < 4; ko++) {
            int kb = ko*8;
            int mr = wm*16 + gp;
            uint32_t ah[4], al[4];
            ah[0] = __float_as_uint(Qhi[mr*SQ     + kb + tg    ]);
            ah[1] = __float_as_uint(Qhi[(mr+8)*SQ + kb + tg    ]);
            ah[2] = __float_as_uint(Qhi[mr*SQ     + kb + tg + 4]);
            ah[3] = __float_as_uint(Qhi[(mr+8)*SQ + kb + tg + 4]);
            al[0] = __float_as_uint(Qlo[mr*SQ     + kb + tg    ]);
            al[1] = __float_as_uint(Qlo[(mr+8)*SQ + kb + tg    ]);
            al[2] = __float_as_uint(Qlo[mr*SQ     + kb + tg + 4]);
            al[3] = __float_as_uint(Qlo[(mr+8)*SQ + kb + tg + 4]);
            #pragma unroll
            for (int tt = 0; tt < 5; tt++) {
                if (tt < cnt) {
                    int nc = (t0 + tt)*8 + gp;
                    uint32_t bb[2];
                    bb[0] = __float_as_uint(Ks[nc*SKV + kb + tg    ]);
                    bb[1] = __float_as_uint(Ks[nc*SKV + kb + tg + 4]);
                    mma_tf32(sacc[tt], ah, bb);
                    mma_tf32(sacc[tt], al, bb);
                }
            }
        }
        #pragma unroll
        for (int tt = 0; tt < 5; tt++) {
            if (tt < cnt) {
                int c  = (t0 + tt)*8 + 2*tg;
                int rr = wm*16 + gp;
                *(float2*)&Sb[rr*SW + c]     = make_float2(sacc[tt][0], sacc[tt][1]);
                *(float2*)&Sb[(rr+8)*SW + c] = make_float2(sacc[tt][2], sacc[tt][3]);
            }
        }
    }
    __syncthreads();

    // ---- softmax per pixel (warp w -> pixels 4w..4w+3, all same row i) ----
    {
        int i  = i0 + wid;
        int si = i - 3; si = si < 0 ? 0 : (si > HH-KS ? HH-KS : si);
        int rb = si - rbase;
        int di = i - si;

        int p0 = lane / KS, c0 = lane % KS;
        int n1 = lane + 32; if (n1 > 48) n1 = 48;
        int p1 = n1 / KS, c1 = n1 % KS;

        #pragma unroll
        for (int lp = 0; lp < 4; lp++) {
            int pix = wid*4 + lp;
            int j  = j0 + lp;
            int sj = j - 3; sj = sj < 0 ? 0 : (sj > WW-KS ? WW-KS : sj);
            int cb = sj - cbase;
            int dj = j - sj;

            int cell0 = (rb + p0)*NCOL + cb + c0;
            int cell1 = (rb + p1)*NCOL + cb + c1;
            float s0 = Sb[pix*SW + cell0] + rpb_s[(p0 + 6 - di)*13 + (c0 + 6 - dj)];
            float s1 = Sb[pix*SW + cell1] + rpb_s[(p1 + 6 - di)*13 + (c1 + 6 - dj)];
            if (lane >= 17) s1 = -1e30f;

            float m = fmaxf(s0, s1);
            #pragma unroll
            for (int o = 16; o > 0; o >>= 1) m = fmaxf(m, __shfl_xor_sync(0xffffffffu, m, o));
            float e0 = __expf(s0 - m);
            float e1 = (lane < 17) ? __expf(s1 - m) : 0.f;
            float se = e0 + e1;
            #pragma unroll
            for (int o = 16; o > 0; o >>= 1) se += __shfl_xor_sync(0xffffffffu, se, o);
            float inv = 1.f / se;
            float w0 = e0 * inv;
            float w1 = e1 * inv;

            __syncwarp();
            // zero the dense row, then scatter weights (hi in Sb, lo in Wl)
            #pragma unroll
            for (int c = lane; c < NCP; c += 32) Sb[pix*SW + c] = 0.f;
            __syncwarp();
            float wh0 = __uint_as_float(f2tf32(w0));
            Sb[pix*SW + cell0] = wh0;
            Wl[pix*SW + cell0] = __uint_as_float(f2tf32(w0 - wh0));
            if (lane < 17) {
                float wh1 = __uint_as_float(f2tf32(w1));
                Sb[pix*SW + cell1] = wh1;
                Wl[pix*SW + cell1] = __uint_as_float(f2tf32(w1 - wh1));
            }
        }
    }
    __syncthreads();

    // ---- AV GEMM: out[32][32] = W @ V ----
    {
        int wm2 = wid & 1;   // m16 tile
        int wn2 = wid >> 1;  // n8 tile (output channels)
        float oacc[4] = {0.f, 0.f, 0.f, 0.f};

        #pragma unroll
        for (int kt = 0; kt < 18; kt++) {
            int kb = kt*8;
            int mr = wm2*16 + gp;
            uint32_t ah[4], al[4], bb[2];
            ah[0] = __float_as_uint(Sb[mr*SW     + kb + tg    ]);
            ah[1] = __float_as_uint(Sb[(mr+8)*SW + kb + tg    ]);
            ah[2] = __float_as_uint(Sb[mr*SW     + kb + tg + 4]);
            ah[3] = __float_as_uint(Sb[(mr+8)*SW + kb + tg + 4]);
            al[0] = __float_as_uint(Wl[mr*SW     + kb + tg    ]);
            al[1] = __float_as_uint(Wl[(mr+8)*SW + kb + tg    ]);
            al[2] = __float_as_uint(Wl[mr*SW     + kb + tg + 4]);
            al[3] = __float_as_uint(Wl[(mr+8)*SW + kb + tg + 4]);
            bb[0] = __float_as_uint(Vs[(kb + tg    )*SKV + wn2*8 + gp]);
            bb[1] = __float_as_uint(Vs[(kb + tg + 4)*SKV + wn2*8 + gp]);
            mma_tf32(oacc, ah, bb);
            mma_tf32(oacc, al, bb);
        }

        int d0 = wn2*8 + 2*tg;
        int pix = wm2*16 + gp;
        int i = i0 + (pix >> 2), j = j0 + (pix & 3);
        int tok = (b*HH + i)*WW + j;
        *(float2*)&out[tok*CC + h*DH + d0] = make_float2(oacc[0], oacc[1]);
        pix += 8;
        i = i0 + (pix >> 2); j = j0 + (pix & 3);
        tok = (b*HH + i)*WW + j;
        *(float2*)&out[tok*CC + h*DH + d0] = make_float2(oacc[2], oacc[3]);
    }
}

// ---------------------------------------------------------------------------
// LayerNorm + NHWC -> NCHW
// ---------------------------------------------------------------------------
__global__ __launch_bounds__(256) void ln_out_kernel(
    const float* __restrict__ y,
    const float* __restrict__ gamma,
    const float* __restrict__ beta,
    float* __restrict__ out)
{
    __shared__ float sh[32][129];
    int tok0 = blockIdx.x * 32;
    int b   = tok0 >> 12;
    int hw0 = tok0 & 4095;
    int w = threadIdx.x >> 5, lane = threadIdx.x & 31;

    #pragma unroll
    for (int t = w*4; t < w*4 + 4; t++) {
        int tok = tok0 + t;
        float v0 = y[tok*CC + lane];
        float v1 = y[tok*CC + lane + 32];
        float v2 = y[tok*CC + lane + 64];
        float v3 = y[tok*CC + lane + 96];
        float s  = v0 + v1 + v2 + v3;
        float s2 = v0*v0 + v1*v1 + v2*v2 + v3*v3;
        #pragma unroll
        for (int o = 16; o > 0; o >>= 1) {
            s  += __shfl_xor_sync(0xffffffffu, s,  o);
            s2 += __shfl_xor_sync(0xffffffffu, s2, o);
        }
        float mu  = s * (1.f/128.f);
        float var = s2 * (1.f/128.f) - mu*mu;
        float rs  = rsqrtf(var + 1e-5f);
        sh[t][lane]      = (v0 - mu)*rs*gamma[lane]      + beta[lane];
        sh[t][lane + 32] = (v1 - mu)*rs*gamma[lane + 32] + beta[lane + 32];
        sh[t][lane + 64] = (v2 - mu)*rs*gamma[lane + 64] + beta[lane + 64];
        sh[t][lane + 96] = (v3 - mu)*rs*gamma[lane + 96] + beta[lane + 96];
    }
    __syncthreads();

    for (int c = w; c < CC; c += 8)
        out[((b*CC + c)*(HH*WW)) + hw0 + lane] = sh[lane][c];
}

// ---------------------------------------------------------------------------
// Launch
// ---------------------------------------------------------------------------
extern "C" void kernel_launch(void* const* d_in, const int* in_sizes, int n_in,
                              void* d_out, int out_size)
{
    const float* x      = (const float*)d_in[0];
    const float* qkv_w  = (const float*)d_in[1];
    const float* qkv_b  = (const float*)d_in[2];
    const float* rpb    = (const float*)d_in[3];
    const float* proj_w = (const float*)d_in[4];
    const float* proj_b = (const float*)d_in[5];
    const float* ln_g   = (const float*)d_in[6];
    const float* ln_b   = (const float*)d_in[7];
    float* out = (float*)d_out;

    float *y, *qkv, *att, *wq, *wp;
    cudaGetSymbolAddress((void**)&y,   g_y);
    cudaGetSymbolAddress((void**)&qkv, g_qkv);
    cudaGetSymbolAddress((void**)&att, g_att);
    cudaGetSymbolAddress((void**)&wq,  g_wq);
    cudaGetSymbolAddress((void**)&wp,  g_wp);

    static int smem_set = 0;
    if (!smem_set) {
        cudaFuncSetAttribute(gemm_tc_kernel,
                             cudaFuncAttributeMaxDynamicSharedMemorySize, GEMM_SMEM);
        cudaFuncSetAttribute(attn_tc_kernel,
                             cudaFuncAttributeMaxDynamicSharedMemorySize, ATTN_SMEM);
        smem_set = 1;
    }

    cvt_w_kernel<<<512, 256>>>(qkv_w, proj_w, wq, wp);

    {
        dim3 grid(HH*WW/32, CC/32, BB), block(32, 8);
        transpose_in_kernel<<<grid, block>>>(x, y);
    }

    for (int l = 0; l < 2; l++) {
        {
            dim3 grid(TOKENS/64, 384/64);
            gemm_tc_kernel<<<grid, 256, GEMM_SMEM>>>(y, wq + l*384*128, qkv_b + l*384,
                                                     qkv, 384, 1);
        }
        {
            dim3 grid(WW/TJ, HH/TI, BB*NH);
            attn_tc_kernel<<<grid, 256, ATTN_SMEM>>>(qkv, rpb + l*NH*13*13, att);
        }
        {
            dim3 grid(TOKENS/64, 128/64);
            gemm_tc_kernel<<<grid, 256, GEMM_SMEM>>>(att, wp + l*128*128, proj_b + l*128,
                                                     y, 128, 0);
        }
    }

    ln_out_kernel<<<TOKENS/32, 256>>>(y, ln_g, ln_b, out);
}

// round 10
// speedup vs baseline: 1.1571x; 1.1571x over previous
#include <cuda_runtime.h>
#include <math.h>
#include <stdint.h>

// Problem constants
#define BB 2
#define CC 128
#define HH 64
#define WW 64
#define NH 4
#define DH 32
#define KS 7
#define TOKENS (BB*HH*WW)   // 8192

// Attention tile config
#define TI 8
#define TJ 4
#define NROW 14
#define NCOL 10
#define NPIX (NROW*NCOL)    // 140
#define SKV 36              // K/V/Q smem stride (float4-aligned, 4 mod 32)
#define SWS 52              // weight smem stride

// Scratch (device globals: no allocation allowed)
__device__ float g_y[TOKENS*CC];
__device__ float g_qkv[TOKENS*3*CC];
__device__ float g_att[TOKENS*CC];
__device__ float g_wq[2*384*128];   // tf32-rounded qkv weights
__device__ float g_wp[2*128*128];   // tf32-rounded proj weights

__device__ __forceinline__ uint32_t f2tf32(float x)
{
    uint32_t r;
    asm("cvt.rna.tf32.f32 %0, %1;" : "=r"(r) : "f"(x));
    return r;
}

__device__ __forceinline__ void mma_tf32(float* d, const uint32_t* a, const uint32_t* b)
{
    asm volatile("mma.sync.aligned.m16n8k8.row.col.f32.tf32.tf32.f32 "
        "{%0,%1,%2,%3}, {%4,%5,%6,%7}, {%8,%9}, {%0,%1,%2,%3};"
        : "+f"(d[0]), "+f"(d[1]), "+f"(d[2]), "+f"(d[3])
        : "r"(a[0]), "r"(a[1]), "r"(a[2]), "r"(a[3]), "r"(b[0]), "r"(b[1]));
}

// ---------------------------------------------------------------------------
// One-shot weight conversion fp32 -> tf32 bit pattern
// ---------------------------------------------------------------------------
__global__ void cvt_w_kernel(const float* __restrict__ qkv_w,
                             const float* __restrict__ proj_w,
                             float* __restrict__ wq,
                             float* __restrict__ wp)
{
    int idx = blockIdx.x * blockDim.x + threadIdx.x;
    const int NQ = 2*384*128;
    const int NP = 2*128*128;
    if (idx < NQ)
        wq[idx] = __uint_as_float(f2tf32(qkv_w[idx]));
    else if (idx < NQ + NP)
        wp[idx - NQ] = __uint_as_float(f2tf32(proj_w[idx - NQ]));
}

// ---------------------------------------------------------------------------
// NCHW -> NHWC transpose
// ---------------------------------------------------------------------------
__global__ void transpose_in_kernel(const float* __restrict__ x, float* __restrict__ y)
{
    __shared__ float tile[32][33];
    int b   = blockIdx.z;
    int hw0 = blockIdx.x * 32;
    int c0  = blockIdx.y * 32;
    int tx = threadIdx.x, ty = threadIdx.y;
    #pragma unroll
    for (int k = 0; k < 32; k += 8)
        tile[ty + k][tx] = x[((b*CC + c0 + ty + k) * (HH*WW)) + hw0 + tx];
    __syncthreads();
    #pragma unroll
    for (int k = 0; k < 32; k += 8)
        y[(b*(HH*WW) + hw0 + ty + k)*CC + c0 + tx] = tile[tx][ty + k];
}

// ---------------------------------------------------------------------------
// tf32 tensor-core GEMM, single-stage full-K smem. (unchanged from R6)
// ---------------------------------------------------------------------------
#define SK 132

__global__ __launch_bounds__(256) void gemm_tc_kernel(
    const float* __restrict__ A,
    const float* __restrict__ W,      // tf32 bits
    const float* __restrict__ bias,
    float* __restrict__ C,
    int N, int scale_q)
{
    extern __shared__ uint32_t smg[];
    uint32_t* As = smg;
    uint32_t* Bs = smg + 64*SK;

    int m0 = blockIdx.x * 64;
    int n0 = blockIdx.y * 64;
    int tid  = threadIdx.x;
    int lane = tid & 31;
    int wid  = tid >> 5;
    int wm = wid & 1;
    int wn = wid >> 1;
    int gp = lane >> 2;
    int tg = lane & 3;

    const float* Ag = A + (m0 + wid)*128 + lane*4;
    const float* Wg = W + (n0 + wid)*128 + lane*4;
    #pragma unroll
    for (int s = 0; s < 8; s++) {
        float4 a = *(const float4*)(Ag + s*8*128);
        float4 b = *(const float4*)(Wg + s*8*128);
        uint4 ua = make_uint4(f2tf32(a.x), f2tf32(a.y), f2tf32(a.z), f2tf32(a.w));
        uint4 ub = make_uint4(__float_as_uint(b.x), __float_as_uint(b.y),
                              __float_as_uint(b.z), __float_as_uint(b.w));
        *(uint4*)&As[(wid + s*8)*SK + lane*4] = ua;
        *(uint4*)&Bs[(wid + s*8)*SK + lane*4] = ub;
    }
    __syncthreads();

    float acc[2][2][4];
    #pragma unroll
    for (int mt = 0; mt < 2; mt++)
        #pragma unroll
        for (int nt = 0; nt < 2; nt++)
            #pragma unroll
            for (int c = 0; c < 4; c++) acc[mt][nt][c] = 0.f;

    #pragma unroll
    for (int ks = 0; ks < 16; ks++) {
        int kb = ks*8;
        uint32_t af[2][4], bf[2][2];
        #pragma unroll
        for (int mt = 0; mt < 2; mt++) {
            int r = wm*32 + mt*16 + gp;
            af[mt][0] = As[r*SK     + kb + tg    ];
            af[mt][1] = As[(r+8)*SK + kb + tg    ];
            af[mt][2] = As[r*SK     + kb + tg + 4];
            af[mt][3] = As[(r+8)*SK + kb + tg + 4];
        }
        #pragma unroll
        for (int nt = 0; nt < 2; nt++) {
            int c = wn*16 + nt*8 + gp;
            bf[nt][0] = Bs[c*SK + kb + tg    ];
            bf[nt][1] = Bs[c*SK + kb + tg + 4];
        }
        #pragma unroll
        for (int mt = 0; mt < 2; mt++)
            #pragma unroll
            for (int nt = 0; nt < 2; nt++)
                mma_tf32(acc[mt][nt], af[mt], bf[nt]);
    }

    const float qs = 0.17677669529663687f;
    #pragma unroll
    for (int mt = 0; mt < 2; mt++) {
        int rbase = m0 + wm*32 + mt*16 + gp;
        #pragma unroll
        for (int nt = 0; nt < 2; nt++) {
            int col = n0 + wn*16 + nt*8 + 2*tg;
            float b0 = bias[col], b1 = bias[col + 1];
            float sc = (scale_q && col < 128) ? qs : 1.f;
            float2 v0 = make_float2((acc[mt][nt][0] + b0)*sc, (acc[mt][nt][1] + b1)*sc);
            float2 v1 = make_float2((acc[mt][nt][2] + b0)*sc, (acc[mt][nt][3] + b1)*sc);
            *(float2*)&C[rbase*N + col]       = v0;
            *(float2*)&C[(rbase + 8)*N + col] = v1;
        }
    }
}
#define GEMM_SMEM (2*64*SK*4)

// ---------------------------------------------------------------------------
// Scalar neighborhood attention v3: vectorized LDS.
// Block = (head, 8x4 pixel tile), 256 threads, warp w -> pixel row i0+w.
// QK: lane = neighbor, float4 K rows + float4 broadcast Q.
// AV: 4 pixels per warp simultaneously; lane = (pixel, 4-channel group);
//     weights broadcast from smem, V as float4.  All fp32.
// ---------------------------------------------------------------------------
#define ATTN_SMEM ((32*SKV + 2*NPIX*SKV + 32*SWS + 176)*4)

__global__ __launch_bounds__(256) void attn_kernel(
    const float* __restrict__ qkv,
    const float* __restrict__ rpb,
    float* __restrict__ out)
{
    extern __shared__ float sma[];
    float* Qs = sma;                    // [32][SKV]
    float* Ks = Qs + 32*SKV;            // [NPIX][SKV]
    float* Vs = Ks + NPIX*SKV;          // [NPIX][SKV]
    float* Ws = Vs + NPIX*SKV;          // [32][SWS]  softmax weights
    float* rpb_s = Ws + 32*SWS;         // [169]

    int j0 = blockIdx.x * TJ;
    int i0 = blockIdx.y * TI;
    int bh = blockIdx.z;
    int b  = bh >> 2;
    int h  = bh & 3;

    int tid  = threadIdx.x;
    int wid  = tid >> 5;
    int lane = tid & 31;

    int rbase = i0 - 3; rbase = rbase < 0 ? 0 : (rbase > HH-NROW ? HH-NROW : rbase);
    int cbase = j0 - 3; cbase = cbase < 0 ? 0 : (cbase > WW-NCOL ? WW-NCOL : cbase);

    // ---- stage Q, K, V, rpb (coalesced, lane = channel) ----
    for (int pix = wid; pix < 32; pix += 8) {
        int i = i0 + (pix >> 2), j = j0 + (pix & 3);
        Qs[pix*SKV + lane] = qkv[((b*HH + i)*WW + j)*384 + h*DH + lane];
    }
    for (int r = wid; r < NPIX; r += 8) {
        int gi = r / NCOL, gj = r % NCOL;
        const float* base = qkv + (((b*HH + rbase + gi)*WW) + cbase + gj)*384 + h*DH;
        Ks[r*SKV + lane] = base[128 + lane];
        Vs[r*SKV + lane] = base[256 + lane];
    }
    if (tid < 169) rpb_s[tid] = rpb[h*169 + tid];
    __syncthreads();

    int i  = i0 + wid;
    int si = i - 3; si = si < 0 ? 0 : (si > HH-KS ? HH-KS : si);
    int rb = si - rbase;
    int di = i - si;

    // neighbor decomposition for this lane
    int p0 = lane / KS, c0 = lane % KS;
    int n1 = lane + 32; if (n1 > 48) n1 = 48;
    int p1 = n1 / KS, c1 = n1 % KS;
    float bias0 = rpb_s[(p0 + 6 - di)*13 + c0*1];   // column part added per-pixel below
    // (row part of rpb index is pixel-independent; col part depends on dj)

    // ---- QK + softmax per pixel; weights -> smem ----
    #pragma unroll
    for (int lj = 0; lj < TJ; lj++) {
        int pix = wid*4 + lj;
        int j  = j0 + lj;
        int sj = j - 3; sj = sj < 0 ? 0 : (sj > WW-KS ? WW-KS : sj);
        int cb = sj - cbase;
        int dj = j - sj;

        int cell0 = (rb + p0)*NCOL + cb + c0;
        int cell1 = (rb + p1)*NCOL + cb + c1;
        const float4* qv = (const float4*)&Qs[pix*SKV];
        const float4* k0 = (const float4*)&Ks[cell0*SKV];
        const float4* k1 = (const float4*)&Ks[cell1*SKV];

        float s0 = 0.f, s1 = 0.f;
        #pragma unroll
        for (int t = 0; t < 8; t++) {
            float4 q = qv[t];
            float4 a = k0[t];
            float4 bv = k1[t];
            s0 = fmaf(q.x, a.x, fmaf(q.y, a.y, fmaf(q.z, a.z, fmaf(q.w, a.w, s0))));
            s1 = fmaf(q.x, bv.x, fmaf(q.y, bv.y, fmaf(q.z, bv.z, fmaf(q.w, bv.w, s1))));
        }
        s0 += rpb_s[(p0 + 6 - di)*13 + (c0 + 6 - dj)];
        s1 += rpb_s[(p1 + 6 - di)*13 + (c1 + 6 - dj)];
        if (lane >= 17) s1 = -1e30f;

        float m = fmaxf(s0, s1);
        #pragma unroll
        for (int o = 16; o > 0; o >>= 1) m = fmaxf(m, __shfl_xor_sync(0xffffffffu, m, o));
        float e0 = __expf(s0 - m);
        float e1 = (lane < 17) ? __expf(s1 - m) : 0.f;
        float se = e0 + e1;
        #pragma unroll
        for (int o = 16; o > 0; o >>= 1) se += __shfl_xor_sync(0xffffffffu, se, o);
        float inv = 1.f / se;
        Ws[pix*SWS + lane] = e0 * inv;
        if (lane < 17) Ws[pix*SWS + 32 + lane] = e1 * inv;
    }
    __syncwarp();

    // ---- AV: lane = (pixel pl, channel group dg); 4 pixels at once ----
    {
        int pl = lane >> 3;          // pixel within warp row
        int dg = lane & 7;           // float4 channel group
        int pix = wid*4 + pl;
        int j  = j0 + pl;
        int sj = j - 3; sj = sj < 0 ? 0 : (sj > WW-KS ? WW-KS : sj);
        int cb = sj - cbase;

        const float* wrow = Ws + pix*SWS;
        float4 acc = make_float4(0.f, 0.f, 0.f, 0.f);

        #pragma unroll
        for (int p = 0; p < KS; p++) {
            int cellb = (rb + p)*NCOL + cb;
            #pragma unroll
            for (int c = 0; c < KS; c++) {
                float w = wrow[p*KS + c];
                float4 v = *(const float4*)&Vs[(cellb + c)*SKV + dg*4];
                acc.x = fmaf(w, v.x, acc.x);
                acc.y = fmaf(w, v.y, acc.y);
                acc.z = fmaf(w, v.z, acc.z);
                acc.w = fmaf(w, v.w, acc.w);
            }
        }
        int tok = (b*HH + i)*WW + j;
        *(float4*)&out[tok*CC + h*DH + dg*4] = acc;
    }
}

// ---------------------------------------------------------------------------
// LayerNorm + NHWC -> NCHW
// ---------------------------------------------------------------------------
__global__ __launch_bounds__(256) void ln_out_kernel(
    const float* __restrict__ y,
    const float* __restrict__ gamma,
    const float* __restrict__ beta,
    float* __restrict__ out)
{
    __shared__ float sh[32][129];
    int tok0 = blockIdx.x * 32;
    int b   = tok0 >> 12;
    int hw0 = tok0 & 4095;
    int w = threadIdx.x >> 5, lane = threadIdx.x & 31;

    #pragma unroll
    for (int t = w*4; t < w*4 + 4; t++) {
        int tok = tok0 + t;
        float v0 = y[tok*CC + lane];
        float v1 = y[tok*CC + lane + 32];
        float v2 = y[tok*CC + lane + 64];
        float v3 = y[tok*CC + lane + 96];
        float s  = v0 + v1 + v2 + v3;
        float s2 = v0*v0 + v1*v1 + v2*v2 + v3*v3;
        #pragma unroll
        for (int o = 16; o > 0; o >>= 1) {
            s  += __shfl_xor_sync(0xffffffffu, s,  o);
            s2 += __shfl_xor_sync(0xffffffffu, s2, o);
        }
        float mu  = s * (1.f/128.f);
        float var = s2 * (1.f/128.f) - mu*mu;
        float rs  = rsqrtf(var + 1e-5f);
        sh[t][lane]      = (v0 - mu)*rs*gamma[lane]      + beta[lane];
        sh[t][lane + 32] = (v1 - mu)*rs*gamma[lane + 32] + beta[lane + 32];
        sh[t][lane + 64] = (v2 - mu)*rs*gamma[lane + 64] + beta[lane + 64];
        sh[t][lane + 96] = (v3 - mu)*rs*gamma[lane + 96] + beta[lane + 96];
    }
    __syncthreads();

    for (int c = w; c < CC; c += 8)
        out[((b*CC + c)*(HH*WW)) + hw0 + lane] = sh[lane][c];
}

// ---------------------------------------------------------------------------
// Launch
// ---------------------------------------------------------------------------
extern "C" void kernel_launch(void* const* d_in, const int* in_sizes, int n_in,
                              void* d_out, int out_size)
{
    const float* x      = (const float*)d_in[0];
    const float* qkv_w  = (const float*)d_in[1];
    const float* qkv_b  = (const float*)d_in[2];
    const float* rpb    = (const float*)d_in[3];
    const float* proj_w = (const float*)d_in[4];
    const float* proj_b = (const float*)d_in[5];
    const float* ln_g   = (const float*)d_in[6];
    const float* ln_b   = (const float*)d_in[7];
    float* out = (float*)d_out;

    float *y, *qkv, *att, *wq, *wp;
    cudaGetSymbolAddress((void**)&y,   g_y);
    cudaGetSymbolAddress((void**)&qkv, g_qkv);
    cudaGetSymbolAddress((void**)&att, g_att);
    cudaGetSymbolAddress((void**)&wq,  g_wq);
    cudaGetSymbolAddress((void**)&wp,  g_wp);

    static int smem_set = 0;
    if (!smem_set) {
        cudaFuncSetAttribute(gemm_tc_kernel,
                             cudaFuncAttributeMaxDynamicSharedMemorySize, GEMM_SMEM);
        cudaFuncSetAttribute(attn_kernel,
                             cudaFuncAttributeMaxDynamicSharedMemorySize, ATTN_SMEM);
        smem_set = 1;
    }

    cvt_w_kernel<<<512, 256>>>(qkv_w, proj_w, wq, wp);

    {
        dim3 grid(HH*WW/32, CC/32, BB), block(32, 8);
        transpose_in_kernel<<<grid, block>>>(x, y);
    }

    for (int l = 0; l < 2; l++) {
        {
            dim3 grid(TOKENS/64, 384/64);
            gemm_tc_kernel<<<grid, 256, GEMM_SMEM>>>(y, wq + l*384*128, qkv_b + l*384,
                                                     qkv, 384, 1);
        }
        {
            dim3 grid(WW/TJ, HH/TI, BB*NH);
            attn_kernel<<<grid, 256, ATTN_SMEM>>>(qkv, rpb + l*NH*13*13, att);
        }
        {
            dim3 grid(TOKENS/64, 128/64);
            gemm_tc_kernel<<<grid, 256, GEMM_SMEM>>>(att, wp + l*128*128, proj_b + l*128,
                                                     y, 128, 0);
        }
    }

    ln_out_kernel<<<TOKENS/32, 256>>>(y, ln_g, ln_b, out);
}